// round 2
// baseline (speedup 1.0000x reference)
#include <cuda_runtime.h>
#include <cstdint>

// Problem constants
#define B 32
#define N 4096
#define KDIM 4096
#define KK 32            // k-chunk per pipeline stage
#define NCHUNK (KDIM / KK)   // 128
#define TO 256           // output tile per block
#define KS_QKV 6
#define KS_P 18
#define SLABS 18
#define LOG2E 1.4426950408889634f

// Scratch (static device allocations — allowed)
__device__ float g_part[SLABS][B][N];   // partial GEMM sums
__device__ float g_h[B][N];             // h = silu(x + attended)

__device__ __forceinline__ uint32_t sm_u32(const void* p) {
    return (uint32_t)__cvta_generic_to_shared(p);
}
#define CP_ASYNC16(dst, src) \
    asm volatile("cp.async.cg.shared.global [%0], [%1], 16;" :: "r"(dst), "l"(src))
#define CP_COMMIT() asm volatile("cp.async.commit_group;")

__device__ __forceinline__ float fast_exp2(float x) {
    float y;
    asm("ex2.approx.ftz.f32 %0, %1;" : "=f"(y) : "f"(x));
    return y;
}

// ---------------------------------------------------------------------------
// GEMM: out_partial[slab][b][o] = sum_{k in my K-range} X[b,k] * W[o,k]
// Tile: TO=256 outputs x all 32 batches. 256 threads: lane og=tid&31 owns
// outputs {obase + og + 32*oi}, warp bg=tid>>5 owns batches {bg*4 .. bg*4+3}.
// Double-buffered cp.async pipeline on 32-wide k-chunks.
// smem rows padded to 36 floats: 16B-aligned float4, conflict-free per
// quarter-warp phase (bank = 4*og + c distinct for og 0..7).
// ---------------------------------------------------------------------------
__global__ __launch_bounds__(256) void gemm_kernel(
    const float* __restrict__ X,
    const float* __restrict__ W0, const float* __restrict__ W1,
    const float* __restrict__ W2,
    int KS)
{
    extern __shared__ float sm[];
    float* Wb0 = sm;                       // [256][36]
    float* Wb1 = sm + TO * 36;
    float* Xb0 = sm + 2 * TO * 36;         // [32][36]
    float* Xb1 = Xb0 + B * 36;

    const float* W = (blockIdx.y == 0) ? W0 : ((blockIdx.y == 1) ? W1 : W2);
    const int obase = blockIdx.x * TO;
    const int s = blockIdx.z;
    const int c0 = (NCHUNK * s) / KS;
    const int c1 = (NCHUNK * (s + 1)) / KS;

    const int tid = threadIdx.x;
    const int og = tid & 31;
    const int bg = tid >> 5;

    // per-thread load slots
    const int lo = tid >> 3;        // W: o row 0..255 (8 rows per i-step below)
    const int lkq = tid & 7;        // float4 col within 32-wide chunk
    const int xb = tid >> 3;        // X: batch row 0..31
    // (xb uses same mapping; 256 threads cover 32 rows x 8 cols)

    // --- prefetch chunk c0 into buffer 0 ---
    {
        const int c = c0;
        #pragma unroll
        for (int i = 0; i < 8; i++) {
            int o = lo + i * 32;  // slot rows: 8 groups of 32 rows
            uint32_t dst = sm_u32(&Wb0[o * 36 + lkq * 4]);
            const float* src = W + (size_t)(obase + o) * KDIM + c * KK + lkq * 4;
            CP_ASYNC16(dst, src);
        }
        {
            uint32_t dst = sm_u32(&Xb0[xb * 36 + lkq * 4]);
            const float* src = X + (size_t)xb * KDIM + c * KK + lkq * 4;
            CP_ASYNC16(dst, src);
        }
        CP_COMMIT();
    }

    float acc[8][4];
    #pragma unroll
    for (int oi = 0; oi < 8; oi++)
        #pragma unroll
        for (int bi = 0; bi < 4; bi++) acc[oi][bi] = 0.0f;

    int cur = 0;
    for (int c = c0; c < c1; c++) {
        const bool has_next = (c + 1) < c1;
        if (has_next) {
            float* Wn = cur ? Wb0 : Wb1;
            float* Xn = cur ? Xb0 : Xb1;
            const int cn = c + 1;
            #pragma unroll
            for (int i = 0; i < 8; i++) {
                int o = lo + i * 32;
                uint32_t dst = sm_u32(&Wn[o * 36 + lkq * 4]);
                const float* src = W + (size_t)(obase + o) * KDIM + cn * KK + lkq * 4;
                CP_ASYNC16(dst, src);
            }
            {
                uint32_t dst = sm_u32(&Xn[xb * 36 + lkq * 4]);
                const float* src = X + (size_t)xb * KDIM + cn * KK + lkq * 4;
                CP_ASYNC16(dst, src);
            }
            CP_COMMIT();
            asm volatile("cp.async.wait_group 1;");
        } else {
            asm volatile("cp.async.wait_group 0;");
        }
        __syncthreads();

        const float* Ws = cur ? Wb1 : Wb0;
        const float* Xs = cur ? Xb1 : Xb0;

        #pragma unroll 2
        for (int kq = 0; kq < 8; kq++) {
            float4 xv[4];
            #pragma unroll
            for (int i = 0; i < 4; i++)
                xv[i] = *(const float4*)&Xs[(bg * 4 + i) * 36 + kq * 4];
            #pragma unroll
            for (int oi = 0; oi < 8; oi++) {
                float4 wv = *(const float4*)&Ws[(og + 32 * oi) * 36 + kq * 4];
                #pragma unroll
                for (int i = 0; i < 4; i++) {
                    acc[oi][i] = fmaf(wv.x, xv[i].x, acc[oi][i]);
                    acc[oi][i] = fmaf(wv.y, xv[i].y, acc[oi][i]);
                    acc[oi][i] = fmaf(wv.z, xv[i].z, acc[oi][i]);
                    acc[oi][i] = fmaf(wv.w, xv[i].w, acc[oi][i]);
                }
            }
        }
        __syncthreads();   // protect buffer 'cur' before it is refilled
        cur ^= 1;
    }

    // epilogue: write partials (coalesced: lanes og -> consecutive o)
    const int slab = blockIdx.y * KS + s;
    #pragma unroll
    for (int oi = 0; oi < 8; oi++) {
        int o = obase + og + 32 * oi;
        #pragma unroll
        for (int bi = 0; bi < 4; bi++) {
            g_part[slab][bg * 4 + bi][o] = acc[oi][bi];
        }
    }
}

// ---------------------------------------------------------------------------
// Attention + first SiLU.
// Block (i_chunk, batch): caches k*log2e and v in smem; each thread owns one
// row i and runs the 4096-j exp loop (MUFU-bound). No max-subtraction needed:
// |q*k| <= ~40 << 88, and exp(max) cancels in the num/den ratio.
// ---------------------------------------------------------------------------
__global__ __launch_bounds__(256) void attn_kernel(
    const float* __restrict__ X,
    const float* __restrict__ bq,
    const float* __restrict__ bk,
    const float* __restrict__ bv)
{
    __shared__ float ksm[N];
    __shared__ float vsm[N];
    const int b = blockIdx.y;
    const int tid = threadIdx.x;

    for (int j = tid; j < N; j += 256) {
        float kv = bk[j], vv = bv[j];
        #pragma unroll
        for (int s = 0; s < KS_QKV; s++) {
            kv += g_part[KS_QKV + s][b][j];        // k slabs 6..11
            vv += g_part[2 * KS_QKV + s][b][j];    // v slabs 12..17
        }
        ksm[j] = kv * LOG2E;
        vsm[j] = vv;
    }
    __syncthreads();

    const int i = blockIdx.x * 256 + tid;
    float q = bq[i];
    #pragma unroll
    for (int s = 0; s < KS_QKV; s++) q += g_part[s][b][i];   // q slabs 0..5

    float num0 = 0.f, num1 = 0.f, num2 = 0.f, num3 = 0.f;
    float den0 = 0.f, den1 = 0.f, den2 = 0.f, den3 = 0.f;
    const float4* k4 = (const float4*)ksm;
    const float4* v4 = (const float4*)vsm;
    #pragma unroll 2
    for (int j4 = 0; j4 < N / 4; j4++) {
        float4 kk = k4[j4];
        float4 vv = v4[j4];
        float e0 = fast_exp2(q * kk.x);
        float e1 = fast_exp2(q * kk.y);
        float e2 = fast_exp2(q * kk.z);
        float e3 = fast_exp2(q * kk.w);
        den0 += e0; den1 += e1; den2 += e2; den3 += e3;
        num0 = fmaf(e0, vv.x, num0);
        num1 = fmaf(e1, vv.y, num1);
        num2 = fmaf(e2, vv.z, num2);
        num3 = fmaf(e3, vv.w, num3);
    }
    float num = (num0 + num1) + (num2 + num3);
    float den = (den0 + den1) + (den2 + den3);
    float att = num / den;

    float z = X[(size_t)b * N + i] + att;
    float sg = 1.0f / (1.0f + fast_exp2(-z * LOG2E));
    g_h[b][i] = z * sg;
}

// ---------------------------------------------------------------------------
// Final reduce: out = silu(h + (h @ Wp^T + bp))
// ---------------------------------------------------------------------------
__global__ __launch_bounds__(256) void final_kernel(
    const float* __restrict__ bp, float* __restrict__ out)
{
    const int idx = blockIdx.x * 256 + threadIdx.x;  // 0 .. 131071
    const int b = idx >> 12;
    const int o = idx & (N - 1);
    float p = bp[o];
    #pragma unroll
    for (int s = 0; s < SLABS; s++) p += g_part[s][b][o];
    float z = g_h[b][o] + p;
    float sg = 1.0f / (1.0f + fast_exp2(-z * LOG2E));
    out[idx] = z * sg;
}

// ---------------------------------------------------------------------------
extern "C" void kernel_launch(void* const* d_in, const int* in_sizes, int n_in,
                              void* d_out, int out_size)
{
    const float* x  = (const float*)d_in[0];
    const float* Wq = (const float*)d_in[1];
    const float* bq = (const float*)d_in[2];
    const float* Wk = (const float*)d_in[3];
    const float* bk = (const float*)d_in[4];
    const float* Wv = (const float*)d_in[5];
    const float* bv = (const float*)d_in[6];
    const float* Wp = (const float*)d_in[7];
    const float* bp = (const float*)d_in[8];
    float* out = (float*)d_out;

    const int smem_bytes = (2 * TO * 36 + 2 * B * 36) * (int)sizeof(float); // 82944
    cudaFuncSetAttribute(gemm_kernel,
                         cudaFuncAttributeMaxDynamicSharedMemorySize, smem_bytes);

    void* hptr = nullptr;
    cudaGetSymbolAddress(&hptr, g_h);

    // q,k,v GEMMs: grid (16 o-tiles, 3 matrices, 6 K-splits) = 288 blocks
    gemm_kernel<<<dim3(N / TO, 3, KS_QKV), 256, smem_bytes>>>(x, Wq, Wk, Wv, KS_QKV);
    // attention + silu -> g_h
    attn_kernel<<<dim3(N / 256, B), 256>>>(x, bq, bk, bv);
    // projection GEMM on h: grid (16, 1, 18) = 288 blocks
    gemm_kernel<<<dim3(N / TO, 1, KS_P), 256, smem_bytes>>>(
        (const float*)hptr, Wp, Wp, Wp, KS_P);
    // final reduce + silu
    final_kernel<<<(B * N) / 256, 256>>>(bp, out);
}

// round 4
// speedup vs baseline: 1.2634x; 1.2634x over previous
#include <cuda_runtime.h>
#include <cstdint>

// Problem constants
#define B 32
#define N 4096
#define KDIM 4096
#define KK 32            // k-chunk per pipeline stage
#define NCHUNK (KDIM / KK)   // 128
#define TO 256           // output tile per block
#define KS_QKV 6
#define KS_P 18
#define SLABS 18
#define NBINS 128
#define LOG2E 1.4426950408889634f

// Scratch (static device allocations — allowed)
__device__ float g_part[SLABS][B][N];   // partial GEMM sums
__device__ float g_h[B][N];             // h = silu(x + attended)
// Per-batch bin moments for rank-1 attention
__device__ float4 g_mD[B][NBINS];       // (D0, D1, D2, D3)  D_m = sum eps^m/m!
__device__ float4 g_mA[B][NBINS];       // (A0, A1, A2, A3)  A_m = sum v*eps^m/m!
__device__ float2 g_mE[B][NBINS];       // (D4, A4)
__device__ float2 g_binfo[B];           // (center of bin 0, delta)

__device__ __forceinline__ uint32_t sm_u32(const void* p) {
    return (uint32_t)__cvta_generic_to_shared(p);
}
#define CP_ASYNC16(dst, src) \
    asm volatile("cp.async.cg.shared.global [%0], [%1], 16;" :: "r"(dst), "l"(src))
#define CP_COMMIT() asm volatile("cp.async.commit_group;")

__device__ __forceinline__ float fast_exp2(float x) {
    float y;
    asm("ex2.approx.ftz.f32 %0, %1;" : "=f"(y) : "f"(x));
    return y;
}

// ---------------------------------------------------------------------------
// GEMM (unchanged from passing R1 kernel)
// ---------------------------------------------------------------------------
__global__ __launch_bounds__(256) void gemm_kernel(
    const float* __restrict__ X,
    const float* __restrict__ W0, const float* __restrict__ W1,
    const float* __restrict__ W2,
    int KS)
{
    extern __shared__ float sm[];
    float* Wb0 = sm;                       // [256][36]
    float* Wb1 = sm + TO * 36;
    float* Xb0 = sm + 2 * TO * 36;         // [32][36]
    float* Xb1 = Xb0 + B * 36;

    const float* W = (blockIdx.y == 0) ? W0 : ((blockIdx.y == 1) ? W1 : W2);
    const int obase = blockIdx.x * TO;
    const int s = blockIdx.z;
    const int c0 = (NCHUNK * s) / KS;
    const int c1 = (NCHUNK * (s + 1)) / KS;

    const int tid = threadIdx.x;
    const int og = tid & 31;
    const int bg = tid >> 5;

    const int lo = tid >> 3;
    const int lkq = tid & 7;
    const int xb = tid >> 3;

    {
        const int c = c0;
        #pragma unroll
        for (int i = 0; i < 8; i++) {
            int o = lo + i * 32;
            uint32_t dst = sm_u32(&Wb0[o * 36 + lkq * 4]);
            const float* src = W + (size_t)(obase + o) * KDIM + c * KK + lkq * 4;
            CP_ASYNC16(dst, src);
        }
        {
            uint32_t dst = sm_u32(&Xb0[xb * 36 + lkq * 4]);
            const float* src = X + (size_t)xb * KDIM + c * KK + lkq * 4;
            CP_ASYNC16(dst, src);
        }
        CP_COMMIT();
    }

    float acc[8][4];
    #pragma unroll
    for (int oi = 0; oi < 8; oi++)
        #pragma unroll
        for (int bi = 0; bi < 4; bi++) acc[oi][bi] = 0.0f;

    int cur = 0;
    for (int c = c0; c < c1; c++) {
        const bool has_next = (c + 1) < c1;
        if (has_next) {
            float* Wn = cur ? Wb0 : Wb1;
            float* Xn = cur ? Xb0 : Xb1;
            const int cn = c + 1;
            #pragma unroll
            for (int i = 0; i < 8; i++) {
                int o = lo + i * 32;
                uint32_t dst = sm_u32(&Wn[o * 36 + lkq * 4]);
                const float* src = W + (size_t)(obase + o) * KDIM + cn * KK + lkq * 4;
                CP_ASYNC16(dst, src);
            }
            {
                uint32_t dst = sm_u32(&Xn[xb * 36 + lkq * 4]);
                const float* src = X + (size_t)xb * KDIM + cn * KK + lkq * 4;
                CP_ASYNC16(dst, src);
            }
            CP_COMMIT();
            asm volatile("cp.async.wait_group 1;");
        } else {
            asm volatile("cp.async.wait_group 0;");
        }
        __syncthreads();

        const float* Ws = cur ? Wb1 : Wb0;
        const float* Xs = cur ? Xb1 : Xb0;

        #pragma unroll 2
        for (int kq = 0; kq < 8; kq++) {
            float4 xv[4];
            #pragma unroll
            for (int i = 0; i < 4; i++)
                xv[i] = *(const float4*)&Xs[(bg * 4 + i) * 36 + kq * 4];
            #pragma unroll
            for (int oi = 0; oi < 8; oi++) {
                float4 wv = *(const float4*)&Ws[(og + 32 * oi) * 36 + kq * 4];
                #pragma unroll
                for (int i = 0; i < 4; i++) {
                    acc[oi][i] = fmaf(wv.x, xv[i].x, acc[oi][i]);
                    acc[oi][i] = fmaf(wv.y, xv[i].y, acc[oi][i]);
                    acc[oi][i] = fmaf(wv.z, xv[i].z, acc[oi][i]);
                    acc[oi][i] = fmaf(wv.w, xv[i].w, acc[oi][i]);
                }
            }
        }
        __syncthreads();
        cur ^= 1;
    }

    const int slab = blockIdx.y * KS + s;
    #pragma unroll
    for (int oi = 0; oi < 8; oi++) {
        int o = obase + og + 32 * oi;
        #pragma unroll
        for (int bi = 0; bi < 4; bi++) {
            g_part[slab][bg * 4 + bi][o] = acc[oi][bi];
        }
    }
}

// ---------------------------------------------------------------------------
// Moments kernel: per batch, reduce k/v from slabs, find k range, bin into
// NBINS bins of power-of-two width, accumulate Taylor moments (with 1/m!
// folded) via per-warp smem-atomic replicas, reduce, write to global.
// ---------------------------------------------------------------------------
__global__ __launch_bounds__(256) void moments_kernel(
    const float* __restrict__ bk, const float* __restrict__ bv)
{
    extern __shared__ float dsm[];
    float* ksm = dsm;                 // [N]
    float* vsm = dsm + N;             // [N]
    float* rep = dsm + 2 * N;         // [8][NBINS][10]
    __shared__ float red[16];

    const int b = blockIdx.x;
    const int tid = threadIdx.x;
    const int w = tid >> 5;
    const int lane = tid & 31;

    // 1. reduce k,v from slabs; local min/max of k
    float kmn = 1e30f, kmx = -1e30f;
    for (int j = tid; j < N; j += 256) {
        float kv = bk[j], vv = bv[j];
        #pragma unroll
        for (int s = 0; s < KS_QKV; s++) {
            kv += g_part[KS_QKV + s][b][j];
            vv += g_part[2 * KS_QKV + s][b][j];
        }
        ksm[j] = kv;
        vsm[j] = vv;
        kmn = fminf(kmn, kv);
        kmx = fmaxf(kmx, kv);
    }
    // warp reduce min/max
    #pragma unroll
    for (int d = 16; d > 0; d >>= 1) {
        kmn = fminf(kmn, __shfl_xor_sync(0xffffffffu, kmn, d));
        kmx = fmaxf(kmx, __shfl_xor_sync(0xffffffffu, kmx, d));
    }
    if (lane == 0) { red[w] = kmn; red[8 + w] = kmx; }

    // 2. zero replicas
    for (int t = tid; t < 8 * NBINS * 10; t += 256) rep[t] = 0.0f;
    __syncthreads();

    float bmn = red[0], bmx = red[8];
    #pragma unroll
    for (int ww = 1; ww < 8; ww++) {
        bmn = fminf(bmn, red[ww]);
        bmx = fmaxf(bmx, red[8 + ww]);
    }
    // power-of-two bin width covering [bmn, bmx] with margin
    float range = fmaxf(bmx - bmn, 1e-6f);
    float dlt = exp2f(ceilf(log2f(range / 126.0f)));
    float kmin_a = floorf(bmn / dlt) * dlt;
    float inv_d = 1.0f / dlt;

    // 3. bin with moments (1/m! folded)
    float* myrep = rep + w * (NBINS * 10);
    for (int j = tid; j < N; j += 256) {
        float k = ksm[j], v = vsm[j];
        float cf = (k - kmin_a) * inv_d;
        int c = (int)cf;
        c = max(0, min(NBINS - 1, c));
        float eps = k - fmaf((float)c + 0.5f, dlt, kmin_a);
        float p1 = eps;
        float p2 = 0.5f * eps * eps;
        float p3 = p2 * eps * (1.0f / 3.0f);
        float p4 = p3 * eps * 0.25f;
        float* r = myrep + c * 10;
        atomicAdd(r + 0, 1.0f);
        atomicAdd(r + 1, p1);
        atomicAdd(r + 2, p2);
        atomicAdd(r + 3, p3);
        atomicAdd(r + 4, p4);
        atomicAdd(r + 5, v);
        atomicAdd(r + 6, v * p1);
        atomicAdd(r + 7, v * p2);
        atomicAdd(r + 8, v * p3);
        atomicAdd(r + 9, v * p4);
    }
    __syncthreads();

    // 4. reduce 8 replicas, write out (one thread per bin)
    if (tid < NBINS) {
        int c = tid;
        float m[10];
        #pragma unroll
        for (int mm = 0; mm < 10; mm++) {
            float s = 0.0f;
            #pragma unroll
            for (int ww = 0; ww < 8; ww++)
                s += rep[ww * (NBINS * 10) + c * 10 + mm];
            m[mm] = s;
        }
        g_mD[b][c] = make_float4(m[0], m[1], m[2], m[3]);
        g_mA[b][c] = make_float4(m[5], m[6], m[7], m[8]);
        g_mE[b][c] = make_float2(m[4], m[9]);
        if (c == 0)
            g_binfo[b] = make_float2(kmin_a + 0.5f * dlt, dlt);
    }
}

// ---------------------------------------------------------------------------
// Attention via bin moments + first SiLU. Per thread: one row i; loop over
// 128 bins: e^{q*kc} * (deg-4 Horner in q) for num and den.
// ---------------------------------------------------------------------------
__global__ __launch_bounds__(256) void attn2_kernel(
    const float* __restrict__ X, const float* __restrict__ bq)
{
    __shared__ float4 Dv[NBINS];
    __shared__ float4 Av[NBINS];
    __shared__ float2 Ev[NBINS];
    const int b = blockIdx.y;
    const int tid = threadIdx.x;

    if (tid < NBINS) {
        Dv[tid] = g_mD[b][tid];
        Av[tid] = g_mA[b][tid];
        Ev[tid] = g_mE[b][tid];
    }
    __syncthreads();

    const int i = blockIdx.x * 256 + tid;
    float q = bq[i];
    #pragma unroll
    for (int s = 0; s < KS_QKV; s++) q += g_part[s][b][i];

    const float2 info = g_binfo[b];
    float kc = info.x;
    const float dlt = info.y;
    const float qL = q * LOG2E;

    float num = 0.0f, den = 0.0f;
    #pragma unroll 4
    for (int c = 0; c < NBINS; c++) {
        float4 D = Dv[c];
        float4 A = Av[c];
        float2 E = Ev[c];
        float e = fast_exp2(qL * kc);
        kc += dlt;   // exact: dlt is a power of two, kc a small multiple of it
        float pd = fmaf(E.x, q, D.w);
        pd = fmaf(pd, q, D.z);
        pd = fmaf(pd, q, D.y);
        pd = fmaf(pd, q, D.x);
        float pa = fmaf(E.y, q, A.w);
        pa = fmaf(pa, q, A.z);
        pa = fmaf(pa, q, A.y);
        pa = fmaf(pa, q, A.x);
        den = fmaf(e, pd, den);
        num = fmaf(e, pa, num);
    }

    float att = num / den;
    float z = X[(size_t)b * N + i] + att;
    float sg = 1.0f / (1.0f + fast_exp2(-z * LOG2E));
    g_h[b][i] = z * sg;
}

// ---------------------------------------------------------------------------
// Final reduce: out = silu(h + (h @ Wp^T + bp))
// ---------------------------------------------------------------------------
__global__ __launch_bounds__(256) void final_kernel(
    const float* __restrict__ bp, float* __restrict__ out)
{
    const int idx = blockIdx.x * 256 + threadIdx.x;
    const int b = idx >> 12;
    const int o = idx & (N - 1);
    float p = bp[o];
    #pragma unroll
    for (int s = 0; s < SLABS; s++) p += g_part[s][b][o];
    float z = g_h[b][o] + p;
    float sg = 1.0f / (1.0f + fast_exp2(-z * LOG2E));
    out[idx] = z * sg;
}

// ---------------------------------------------------------------------------
extern "C" void kernel_launch(void* const* d_in, const int* in_sizes, int n_in,
                              void* d_out, int out_size)
{
    const float* x  = (const float*)d_in[0];
    const float* Wq = (const float*)d_in[1];
    const float* bq = (const float*)d_in[2];
    const float* Wk = (const float*)d_in[3];
    const float* bk = (const float*)d_in[4];
    const float* Wv = (const float*)d_in[5];
    const float* bv = (const float*)d_in[6];
    const float* Wp = (const float*)d_in[7];
    const float* bp = (const float*)d_in[8];
    float* out = (float*)d_out;

    const int smem_bytes = (2 * TO * 36 + 2 * B * 36) * (int)sizeof(float); // 82944
    cudaFuncSetAttribute(gemm_kernel,
                         cudaFuncAttributeMaxDynamicSharedMemorySize, smem_bytes);
    const int mom_smem = (2 * N + 8 * NBINS * 10) * (int)sizeof(float);     // 73728
    cudaFuncSetAttribute(moments_kernel,
                         cudaFuncAttributeMaxDynamicSharedMemorySize, mom_smem);

    void* hptr = nullptr;
    cudaGetSymbolAddress(&hptr, g_h);

    // q,k,v GEMMs
    gemm_kernel<<<dim3(N / TO, 3, KS_QKV), 256, smem_bytes>>>(x, Wq, Wk, Wv, KS_QKV);
    // per-batch bin moments
    moments_kernel<<<B, 256, mom_smem>>>(bk, bv);
    // attention + silu -> g_h
    attn2_kernel<<<dim3(N / 256, B), 256>>>(x, bq);
    // projection GEMM on h
    gemm_kernel<<<dim3(N / TO, 1, KS_P), 256, smem_bytes>>>(
        (const float*)hptr, Wp, Wp, Wp, KS_P);
    // final reduce + silu
    final_kernel<<<(B * N) / 256, 256>>>(bp, out);
}